// round 9
// baseline (speedup 1.0000x reference)
#include <cuda_runtime.h>
#include <cuda_bf16.h>

#define NN 1024
#define DIM 128
#define NM 1023
#define LAMBF 0.9f
#define C0F 0.1f
#define CEXP (-1.0f/450.0f)   /* -0.5 / sigma^2, sigma=15 */
#define K_ITERS 6             /* even: final iterate lands in mct_v0 */
#define SOLVE_BLOCKS 64
#define FLAG_STRIDE 32        /* 128B padding between flags */
#define MR 16                 /* rows per MLP block */
#define MTHR 512              /* MLP threads per block */
#define WS 132                /* W smem stride: 16B-aligned rows */

// ---------------- scratch (static device globals; no allocation) ----------------
__device__ float mct_x[NN*DIM];
__device__ float mct_fmag[NN];
__device__ float mct_xinv[NN];
__device__ float mct_A[NN*NN];        // unnormalized kernel matrix, diag=0 (4 MB)
__device__ float mct_rowsum[NN];
__device__ float mct_v0[NN];          // iterate; v[0] stays 0 forever (zero-init, never written)
__device__ float mct_v1[NN];
__device__ unsigned int mct_flags[SOLVE_BLOCKS*FLAG_STRIDE];
__device__ unsigned int mct_gen;

// ---------------- sync primitives ----------------
__device__ __forceinline__ void st_release_u32(unsigned int* p, unsigned int v) {
    asm volatile("st.release.gpu.global.u32 [%0], %1;" :: "l"(p), "r"(v) : "memory");
}
__device__ __forceinline__ unsigned int ld_acquire_u32(unsigned int* p) {
    unsigned int v;
    asm volatile("ld.acquire.gpu.global.u32 %0, [%1];" : "=r"(v) : "l"(p) : "memory");
    return v;
}
__device__ __forceinline__ float4 ldv_f4(const float* p) {
    float4 v;
    asm volatile("ld.volatile.global.v4.f32 {%0,%1,%2,%3}, [%4];"
                 : "=f"(v.x), "=f"(v.y), "=f"(v.z), "=f"(v.w) : "l"(p) : "memory");
    return v;
}

// ---------------- kernel 1: fused 4-layer MLP + norms; resets state ----------------
// 64 blocks x 512 threads, 16 rows/block, thread = 4 rows x 1 col.
// Weight smem read (512B/warp/k4) amortized over 4 rows -> crossbar traffic halved vs 2-row version.
extern __shared__ float mlp_sm[];

__global__ void __launch_bounds__(MTHR, 1) mlp_kernel(
    const float* __restrict__ f,
    const float* __restrict__ w1, const float* __restrict__ b1,
    const float* __restrict__ w2, const float* __restrict__ b2,
    const float* __restrict__ w3, const float* __restrict__ b3,
    const float* __restrict__ w4, const float* __restrict__ b4)
{
    float* Ws  = mlp_sm;                  // [128][132]
    float* R0  = Ws + DIM * WS;           // [16][128]
    float* R1  = R0 + MR * DIM;           // [16][128]
    int tid = threadIdx.x;
    int lane = tid & 31, warp = tid >> 5;
    int c = tid & 127;                    // output column
    int h = tid >> 7;                     // row quad: rows h*4 .. h*4+3  (h in 0..3)
    int row0 = blockIdx.x * MR;

    // reset per-replay state (stream-ordered before gemm/solve)
    if (blockIdx.x == 0) {
        if (tid < SOLVE_BLOCKS) mct_flags[tid * FLAG_STRIDE] = 0u;
        if (tid == 0) mct_gen = 0u;
    }
    if (tid < MR) mct_rowsum[row0 + tid] = 0.f;

    // load 16 input rows (512 float4 slots, coalesced)
    {
        int rr = tid >> 5, cc = (tid & 31) * 4;
        *(float4*)&R0[rr * DIM + cc] = *(const float4*)&f[(row0 + rr) * DIM + cc];
    }

    const float* Wl[4] = { w2, w3, w4, w1 };
    const float* Bl[4] = { b2, b3, b4, b1 };
    float* bufin = R0;
    float* bufout = R1;

#pragma unroll
    for (int L = 0; L < 4; L++) {
        __syncthreads();
        // stage W as-is: Ws[t][k], stride 132 (4096 float4 slots over 512 threads)
        const float* w = Wl[L];
#pragma unroll
        for (int i = 0; i < 8; i++) {
            int idx = tid + i * MTHR;
            int t = idx >> 5, kc = (idx & 31) * 4;
            float4 v = __ldg((const float4*)&w[t * DIM + kc]);
            *(float4*)&Ws[t * WS + kc] = v;
        }
        __syncthreads();

        float bc = __ldg(&Bl[L][c]);
        float a0 = bc, a1 = bc, a2 = bc, a3 = bc;
        const float4* wc4 = (const float4*)&Ws[c * WS];          // 16B-aligned
        const float4* p0 = (const float4*)&bufin[(h * 4 + 0) * DIM];
        const float4* p1 = (const float4*)&bufin[(h * 4 + 1) * DIM];
        const float4* p2 = (const float4*)&bufin[(h * 4 + 2) * DIM];
        const float4* p3 = (const float4*)&bufin[(h * 4 + 3) * DIM];
#pragma unroll
        for (int k4 = 0; k4 < 32; k4++) {
            float4 wv = wc4[k4];
            float4 v0 = p0[k4];                                  // warp broadcasts
            float4 v1 = p1[k4];
            float4 v2 = p2[k4];
            float4 v3 = p3[k4];
            a0 = fmaf(v0.x, wv.x, a0); a0 = fmaf(v0.y, wv.y, a0);
            a0 = fmaf(v0.z, wv.z, a0); a0 = fmaf(v0.w, wv.w, a0);
            a1 = fmaf(v1.x, wv.x, a1); a1 = fmaf(v1.y, wv.y, a1);
            a1 = fmaf(v1.z, wv.z, a1); a1 = fmaf(v1.w, wv.w, a1);
            a2 = fmaf(v2.x, wv.x, a2); a2 = fmaf(v2.y, wv.y, a2);
            a2 = fmaf(v2.z, wv.z, a2); a2 = fmaf(v2.w, wv.w, a2);
            a3 = fmaf(v3.x, wv.x, a3); a3 = fmaf(v3.y, wv.y, a3);
            a3 = fmaf(v3.z, wv.z, a3); a3 = fmaf(v3.w, wv.w, a3);
        }
        __syncthreads();

        float* outp = (L < 3) ? bufout : R1;   // last layer also buffered for the norm pass
        outp[(h * 4 + 0) * DIM + c] = a0;
        outp[(h * 4 + 1) * DIM + c] = a1;
        outp[(h * 4 + 2) * DIM + c] = a2;
        outp[(h * 4 + 3) * DIM + c] = a3;

        if (L == 3) {
            mct_x[(row0 + h * 4 + 0) * DIM + c] = a0;
            mct_x[(row0 + h * 4 + 1) * DIM + c] = a1;
            mct_x[(row0 + h * 4 + 2) * DIM + c] = a2;
            mct_x[(row0 + h * 4 + 3) * DIM + c] = a3;
        }

        if (L == 2 || L == 3) {
            __syncthreads();
            // norm pass: warps 0..15 reduce rows 0..15 of outp
            float4 v = *(float4*)&outp[warp * DIM + lane * 4];
            float p = v.x * v.x + v.y * v.y + v.z * v.z + v.w * v.w;
#pragma unroll
            for (int o = 16; o; o >>= 1) p += __shfl_xor_sync(0xffffffffu, p, o);
            if (lane == 0) {
                if (L == 2) mct_fmag[row0 + warp] = p;        // |f|^2 after w4
                else        mct_xinv[row0 + warp] = 1.f / p;  // 1/|x|^2 after w1
            }
        }

        if (L < 3) { float* tmp = bufin; bufin = bufout; bufout = tmp; }
    }
}

// ---------------- kernel 2: A = exp(CEXP * fmag_j * (x_i.x_j / |x_j|^2 - 1)^2), diag 0; + row sums ----------------
__global__ void gemm_xxt_kernel()
{
    __shared__ float As[64][33];
    __shared__ float Bs[64][33];
    int tid = threadIdx.x;
    int tx = tid & 15, ty = tid >> 4;
    int lane = tid & 31;
    int bi = blockIdx.y * 64, bj = blockIdx.x * 64;
    float acc[4][4];
#pragma unroll
    for (int i = 0; i < 4; i++)
#pragma unroll
        for (int j = 0; j < 4; j++) acc[i][j] = 0.f;

    for (int k0 = 0; k0 < DIM; k0 += 32) {
#pragma unroll
        for (int l = 0; l < 2; l++) {
            int idx = tid + l * 256;
            int rr = idx >> 3, cc = (idx & 7) * 4;
            float4 va = *(const float4*)&mct_x[(bi + rr) * DIM + k0 + cc];
            As[rr][cc] = va.x; As[rr][cc + 1] = va.y; As[rr][cc + 2] = va.z; As[rr][cc + 3] = va.w;
            float4 vb = *(const float4*)&mct_x[(bj + rr) * DIM + k0 + cc];
            Bs[rr][cc] = vb.x; Bs[rr][cc + 1] = vb.y; Bs[rr][cc + 2] = vb.z; Bs[rr][cc + 3] = vb.w;
        }
        __syncthreads();
#pragma unroll
        for (int k = 0; k < 32; k++) {
            float a[4], b[4];
#pragma unroll
            for (int p = 0; p < 4; p++) { a[p] = As[ty * 4 + p][k]; b[p] = Bs[tx * 4 + p][k]; }
#pragma unroll
            for (int i = 0; i < 4; i++)
#pragma unroll
                for (int j = 0; j < 4; j++) acc[i][j] = fmaf(a[i], b[j], acc[i][j]);
        }
        __syncthreads();
    }

    float xinv_c[4], fmag_c[4];
#pragma unroll
    for (int j = 0; j < 4; j++) {
        int col = bj + tx * 4 + j;
        xinv_c[j] = mct_xinv[col];
        fmag_c[j] = mct_fmag[col];
    }
#pragma unroll
    for (int i = 0; i < 4; i++) {
        int row = bi + ty * 4 + i;
        float av[4];
        float rs = 0.f;
#pragma unroll
        for (int j = 0; j < 4; j++) {
            int col = bj + tx * 4 + j;
            float s = acc[i][j] * xinv_c[j];
            float dm = s - 1.f;
            float a = (row == col) ? 0.f : __expf(CEXP * fmag_c[j] * dm * dm);
            av[j] = a;
            rs += a;
        }
        *(float4*)&mct_A[(size_t)row * NN + bj + tx * 4] = make_float4(av[0], av[1], av[2], av[3]);
#pragma unroll
        for (int o = 8; o; o >>= 1) rs += __shfl_xor_sync(0xffffffffu, rs, o);
        if ((lane & 15) == 0) atomicAdd(&mct_rowsum[row], rs);
    }
}

// ---------------- kernel 3: persistent Neumann iteration + fused finalize ----------------
__global__ void __launch_bounds__(256, 1) solve_kernel(float* __restrict__ out)
{
    int tid = threadIdx.x, warp = tid >> 5, lane = tid & 31;
    int bid = blockIdx.x;
    int r0 = 1 + bid * 16 + warp * 2;   // 1..1023
    int r1 = r0 + 1;
    bool ok1 = (r1 <= NM);
    const float4* A0 = (const float4*)(mct_A + (size_t)r0 * NN);
    const float4* A1 = (const float4*)(mct_A + (size_t)(ok1 ? r1 : r0) * NN);
    const float4* Arow0 = (const float4*)mct_A;   // row 0 (A[0][0]=0)

    float rs0inv = C0F / fmaxf(mct_rowsum[0], 1e-10f);
    float c00 = rs0inv * mct_A[r0];               // C0F * p0[r0]
    float c01 = ok1 ? rs0inv * mct_A[r1] : 0.f;
    float il0 = LAMBF / fmaxf(mct_rowsum[r0], 1e-10f);
    float il1 = ok1 ? LAMBF / fmaxf(mct_rowsum[r1], 1e-10f) : 0.f;

    for (int it = 0; it < K_ITERS; it++) {
        float* xout = (it & 1) ? mct_v0 : mct_v1;

        float4 xv[8];
        if (it == 0) {
            // x0[j] = rs0inv * A[0][j]
#pragma unroll
            for (int k = 0; k < 8; k++) {
                float4 a = __ldg(&Arow0[k * 32 + lane]);
                xv[k] = make_float4(a.x * rs0inv, a.y * rs0inv, a.z * rs0inv, a.w * rs0inv);
            }
        } else {
            const float* xin = (it & 1) ? mct_v1 : mct_v0;
#pragma unroll
            for (int k = 0; k < 8; k++) xv[k] = ldv_f4(xin + (k * 32 + lane) * 4);
        }

        float d0a = 0.f, d0b = 0.f, d1a = 0.f, d1b = 0.f;
#pragma unroll
        for (int k = 0; k < 8; k += 2) {
            float4 m0 = A0[k * 32 + lane];
            float4 m1 = A1[k * 32 + lane];
            float4 n0 = A0[(k + 1) * 32 + lane];
            float4 n1 = A1[(k + 1) * 32 + lane];
            d0a = fmaf(m0.x, xv[k].x, d0a); d0a = fmaf(m0.y, xv[k].y, d0a);
            d0a = fmaf(m0.z, xv[k].z, d0a); d0a = fmaf(m0.w, xv[k].w, d0a);
            d1a = fmaf(m1.x, xv[k].x, d1a); d1a = fmaf(m1.y, xv[k].y, d1a);
            d1a = fmaf(m1.z, xv[k].z, d1a); d1a = fmaf(m1.w, xv[k].w, d1a);
            d0b = fmaf(n0.x, xv[k+1].x, d0b); d0b = fmaf(n0.y, xv[k+1].y, d0b);
            d0b = fmaf(n0.z, xv[k+1].z, d0b); d0b = fmaf(n0.w, xv[k+1].w, d0b);
            d1b = fmaf(n1.x, xv[k+1].x, d1b); d1b = fmaf(n1.y, xv[k+1].y, d1b);
            d1b = fmaf(n1.z, xv[k+1].z, d1b); d1b = fmaf(n1.w, xv[k+1].w, d1b);
        }
        float d0 = d0a + d0b, d1 = d1a + d1b;
#pragma unroll
        for (int o = 16; o; o >>= 1) {
            d0 += __shfl_xor_sync(0xffffffffu, d0, o);
            d1 += __shfl_xor_sync(0xffffffffu, d1, o);
        }
        if (lane == 0) {
            xout[r0] = fmaf(il0, d0, c00);
            if (ok1) xout[r1] = fmaf(il1, d1, c01);
        }

        // ---- hierarchical grid barrier ----
        __syncthreads();
        unsigned int tgt = (unsigned)it + 1u;
        if (warp == 0) {
            if (lane == 0) st_release_u32(&mct_flags[bid * FLAG_STRIDE], tgt);
            if (bid == 0) {
                bool done;
                do {
                    unsigned a = ld_acquire_u32(&mct_flags[lane * FLAG_STRIDE]);
                    unsigned b = ld_acquire_u32(&mct_flags[(lane + 32) * FLAG_STRIDE]);
                    done = __all_sync(0xffffffffu, (a >= tgt) && (b >= tgt));
                } while (!done);
                if (lane == 0) st_release_u32(&mct_gen, tgt);
            } else if (it < K_ITERS - 1) {
                while (ld_acquire_u32(&mct_gen) < tgt) { }
            }
        }
        __syncthreads();
    }

    if (bid != 0) return;

    // ---- fused finalize (block 0 only): mean-center, clip, *100, softmax ----
    __shared__ float red[8];

    float4 vv = ldv_f4(mct_v0 + tid * 4);   // final iterate (K even); idx 0 pad = 0
    float vals[4] = {vv.x, vv.y, vv.z, vv.w};

    float s = vals[0] + vals[1] + vals[2] + vals[3];
#pragma unroll
    for (int o = 16; o; o >>= 1) s += __shfl_xor_sync(0xffffffffu, s, o);
    if (lane == 0) red[warp] = s;
    __syncthreads();
    if (warp == 0) {
        float x = (lane < 8) ? red[lane] : 0.f;
#pragma unroll
        for (int o = 4; o; o >>= 1) x += __shfl_xor_sync(0xffffffffu, x, o);
        if (lane == 0) red[0] = x;
    }
    __syncthreads();
    float mean = red[0] / (float)NM;
    __syncthreads();

    float z[4];
#pragma unroll
    for (int q = 0; q < 4; q++) {
        int idx = tid * 4 + q;
        z[q] = (idx >= 1) ? fmaxf(vals[q] - mean, 0.f) * 100.f : 0.f;
    }

    float m = fmaxf(fmaxf(z[0], z[1]), fmaxf(z[2], z[3]));
#pragma unroll
    for (int o = 16; o; o >>= 1) m = fmaxf(m, __shfl_xor_sync(0xffffffffu, m, o));
    if (lane == 0) red[warp] = m;
    __syncthreads();
    if (warp == 0) {
        float x = (lane < 8) ? red[lane] : 0.f;
#pragma unroll
        for (int o = 4; o; o >>= 1) x = fmaxf(x, __shfl_xor_sync(0xffffffffu, x, o));
        if (lane == 0) red[0] = x;
    }
    __syncthreads();
    float mx = red[0];
    __syncthreads();

    float e[4];
    float se = 0.f;
#pragma unroll
    for (int q = 0; q < 4; q++) {
        int idx = tid * 4 + q;
        e[q] = (idx >= 1) ? expf(z[q] - mx) : 0.f;
        se += e[q];
    }
#pragma unroll
    for (int o = 16; o; o >>= 1) se += __shfl_xor_sync(0xffffffffu, se, o);
    if (lane == 0) red[warp] = se;
    __syncthreads();
    if (warp == 0) {
        float x = (lane < 8) ? red[lane] : 0.f;
#pragma unroll
        for (int o = 4; o; o >>= 1) x += __shfl_xor_sync(0xffffffffu, x, o);
        if (lane == 0) red[0] = x;
    }
    __syncthreads();
    float inv = 1.f / red[0];

#pragma unroll
    for (int q = 0; q < 4; q++) {
        int idx = tid * 4 + q;
        if (idx >= 1) out[idx - 1] = e[q] * inv;
    }
}

// ---------------- launch ----------------
extern "C" void kernel_launch(void* const* d_in, const int* in_sizes, int n_in,
                              void* d_out, int out_size)
{
    const float* f  = (const float*)d_in[0];
    const float* w1 = (const float*)d_in[1]; const float* b1 = (const float*)d_in[2];
    const float* w2 = (const float*)d_in[3]; const float* b2 = (const float*)d_in[4];
    const float* w3 = (const float*)d_in[5]; const float* b3 = (const float*)d_in[6];
    const float* w4 = (const float*)d_in[7]; const float* b4 = (const float*)d_in[8];
    float* out = (float*)d_out;

    const int mlp_smem = (DIM * WS + 2 * MR * DIM) * (int)sizeof(float); // ~82 KB
    cudaFuncSetAttribute(mlp_kernel, cudaFuncAttributeMaxDynamicSharedMemorySize, mlp_smem);

    mlp_kernel<<<NN / MR, MTHR, mlp_smem>>>(f, w1, b1, w2, b2, w3, b3, w4, b4);
    dim3 g(16, 16);
    gemm_xxt_kernel<<<g, 256>>>();
    solve_kernel<<<SOLVE_BLOCKS, 256>>>(out);
}

// round 10
// speedup vs baseline: 1.0984x; 1.0984x over previous
#include <cuda_runtime.h>
#include <cuda_bf16.h>

#define NN 1024
#define DIM 128
#define NM 1023
#define LAMBF 0.9f
#define C0F 0.1f
#define CEXP (-1.0f/450.0f)   /* -0.5 / sigma^2, sigma=15 */
#define K_ITERS 4             /* even: final iterate lands in mct_v0 */
#define NBLK 128
#define THR 256
#define FLAG_STRIDE 32        /* 128B padding between flags */
#define MR 8                  /* rows per block (MLP + solve) */
#define WS 132                /* W smem stride: 16B-aligned rows */
#define GS 68                 /* gemm k-major smem stride: 68*4=272 ≡ 0 mod 16 */

// ---------------- scratch (static device globals; no allocation) ----------------
__device__ float mct_x[NN*DIM];
__device__ float mct_fmag[NN];
__device__ float mct_xinv[NN];
__device__ float mct_A[NN*NN];        // unnormalized kernel matrix, diag=0 (4 MB)
__device__ float mct_rowsum[NN];
__device__ float mct_v0[NN];          // iterate; v[0] stays 0 forever (zero-init, never written)
__device__ float mct_v1[NN];
__device__ unsigned int mct_flags[NBLK*FLAG_STRIDE];   // monotonically increasing epochs
__device__ unsigned int mct_gen;

// ---------------- sync primitives ----------------
__device__ __forceinline__ void st_release_u32(unsigned int* p, unsigned int v) {
    asm volatile("st.release.gpu.global.u32 [%0], %1;" :: "l"(p), "r"(v) : "memory");
}
__device__ __forceinline__ unsigned int ld_acquire_u32(unsigned int* p) {
    unsigned int v;
    asm volatile("ld.acquire.gpu.global.u32 %0, [%1];" : "=r"(v) : "l"(p) : "memory");
    return v;
}
__device__ __forceinline__ float4 ldv_f4(const float* p) {
    float4 v;
    asm volatile("ld.volatile.global.v4.f32 {%0,%1,%2,%3}, [%4];"
                 : "=f"(v.x), "=f"(v.y), "=f"(v.z), "=f"(v.w) : "l"(p) : "memory");
    return v;
}

// Epoch-based grid barrier: every launch publishes exactly (2 + K_ITERS) barriers,
// so each block's flag and gen advance by the same amount per launch. Targets are
// base+n where base = own flag at kernel entry -> no reset needed, replay-safe.
__device__ __forceinline__ void grid_barrier(unsigned int tgt, int bid, int tid, bool do_wait)
{
    __syncthreads();
    if (tid < 32) {
        if (tid == 0) st_release_u32(&mct_flags[bid * FLAG_STRIDE], tgt);
        if (bid == 0) {
            bool done;
            do {
                done = true;
#pragma unroll
                for (int k = 0; k < 4; k++)
                    done &= (ld_acquire_u32(&mct_flags[(tid + 32 * k) * FLAG_STRIDE]) >= tgt);
            } while (!__all_sync(0xffffffffu, done));
            if (tid == 0) st_release_u32(&mct_gen, tgt);
        } else if (do_wait) {
            if (tid == 0) { while (ld_acquire_u32(&mct_gen) < tgt) { } }
        }
    }
    __syncthreads();
}

extern __shared__ float sm[];

__global__ void __launch_bounds__(THR, 1) fused_kernel(
    float* __restrict__ out,
    const float* __restrict__ f,
    const float* __restrict__ w1, const float* __restrict__ b1,
    const float* __restrict__ w2, const float* __restrict__ b2,
    const float* __restrict__ w3, const float* __restrict__ b3,
    const float* __restrict__ w4, const float* __restrict__ b4)
{
    __shared__ unsigned int sbase;
    __shared__ float red[8];
    int tid = threadIdx.x, lane = tid & 31, warp = tid >> 5;
    int bid = blockIdx.x;

    if (tid == 0) sbase = *((volatile unsigned int*)&mct_flags[bid * FLAG_STRIDE]);
    __syncthreads();
    const unsigned int base = sbase;

    // ================= phase 1: fused 4-layer MLP + norms (R7 config) =================
    {
        float* Ws = sm;                   // [128][132]
        float* R0 = Ws + DIM * WS;        // [8][128]
        float* R1 = R0 + MR * DIM;        // [8][128]
        int c = tid & 127;
        int h = tid >> 7;                 // 0..1: rows h*4 .. h*4+3
        int row0 = bid * MR;

        if (tid < MR) mct_rowsum[row0 + tid] = 0.f;

        {
            int rr = tid >> 5, cc = (tid & 31) * 4;
            *(float4*)&R0[rr * DIM + cc] = *(const float4*)&f[(row0 + rr) * DIM + cc];
        }

        const float* Wl[4] = { w2, w3, w4, w1 };
        const float* Bl[4] = { b2, b3, b4, b1 };
        float* bufin = R0;
        float* bufout = R1;

#pragma unroll
        for (int L = 0; L < 4; L++) {
            __syncthreads();
            const float* w = Wl[L];
#pragma unroll
            for (int i = 0; i < 16; i++) {
                int idx = tid + i * THR;
                int t = idx >> 5, kc = (idx & 31) * 4;
                float4 v = __ldg((const float4*)&w[t * DIM + kc]);
                *(float4*)&Ws[t * WS + kc] = v;
            }
            __syncthreads();

            float bc = __ldg(&Bl[L][c]);
            float a0 = bc, a1 = bc, a2 = bc, a3 = bc;
            const float4* wc4 = (const float4*)&Ws[c * WS];
            const float4* p0 = (const float4*)&bufin[(h * 4 + 0) * DIM];
            const float4* p1 = (const float4*)&bufin[(h * 4 + 1) * DIM];
            const float4* p2 = (const float4*)&bufin[(h * 4 + 2) * DIM];
            const float4* p3 = (const float4*)&bufin[(h * 4 + 3) * DIM];
#pragma unroll
            for (int k4 = 0; k4 < 32; k4++) {
                float4 wv = wc4[k4];
                float4 v0 = p0[k4];
                float4 v1 = p1[k4];
                float4 v2 = p2[k4];
                float4 v3 = p3[k4];
                a0 = fmaf(v0.x, wv.x, a0); a0 = fmaf(v0.y, wv.y, a0);
                a0 = fmaf(v0.z, wv.z, a0); a0 = fmaf(v0.w, wv.w, a0);
                a1 = fmaf(v1.x, wv.x, a1); a1 = fmaf(v1.y, wv.y, a1);
                a1 = fmaf(v1.z, wv.z, a1); a1 = fmaf(v1.w, wv.w, a1);
                a2 = fmaf(v2.x, wv.x, a2); a2 = fmaf(v2.y, wv.y, a2);
                a2 = fmaf(v2.z, wv.z, a2); a2 = fmaf(v2.w, wv.w, a2);
                a3 = fmaf(v3.x, wv.x, a3); a3 = fmaf(v3.y, wv.y, a3);
                a3 = fmaf(v3.z, wv.z, a3); a3 = fmaf(v3.w, wv.w, a3);
            }
            __syncthreads();

            float* outp = (L < 3) ? bufout : R1;
            outp[(h * 4 + 0) * DIM + c] = a0;
            outp[(h * 4 + 1) * DIM + c] = a1;
            outp[(h * 4 + 2) * DIM + c] = a2;
            outp[(h * 4 + 3) * DIM + c] = a3;

            if (L == 3) {
                mct_x[(row0 + h * 4 + 0) * DIM + c] = a0;
                mct_x[(row0 + h * 4 + 1) * DIM + c] = a1;
                mct_x[(row0 + h * 4 + 2) * DIM + c] = a2;
                mct_x[(row0 + h * 4 + 3) * DIM + c] = a3;
            }

            if (L == 2 || L == 3) {
                __syncthreads();
                if (warp < MR) {
                    float4 v = *(float4*)&outp[warp * DIM + lane * 4];
                    float p = v.x * v.x + v.y * v.y + v.z * v.z + v.w * v.w;
#pragma unroll
                    for (int o = 16; o; o >>= 1) p += __shfl_xor_sync(0xffffffffu, p, o);
                    if (lane == 0) {
                        if (L == 2) mct_fmag[row0 + warp] = p;        // |f|^2 after w4
                        else        mct_xinv[row0 + warp] = 1.f / p;  // 1/|x|^2 after w1
                    }
                }
            }

            if (L < 3) { float* tmp = bufin; bufin = bufout; bufout = tmp; }
        }
    }

    grid_barrier(base + 1, bid, tid, true);

    // ================= phase 2: GEMM x.x^T + kernel transform (2 tiles/block) =================
    {
        float* As = sm;              // k-major [32][GS]
        float* Bs = sm + 32 * GS;
        int tx = tid & 15, ty = tid >> 4;

#pragma unroll
        for (int tsub = 0; tsub < 2; tsub++) {
            int t = bid * 2 + tsub;
            int bi = (t >> 4) * 64, bj = (t & 15) * 64;
            float acc[4][4];
#pragma unroll
            for (int i = 0; i < 4; i++)
#pragma unroll
                for (int j = 0; j < 4; j++) acc[i][j] = 0.f;

            for (int k0 = 0; k0 < DIM; k0 += 32) {
                __syncthreads();
#pragma unroll
                for (int l = 0; l < 2; l++) {
                    int idx = tid + l * THR;
                    int rr = idx >> 3, cc = (idx & 7) * 4;
                    float4 va = *(const float4*)&mct_x[(bi + rr) * DIM + k0 + cc];
                    As[(cc + 0) * GS + rr] = va.x; As[(cc + 1) * GS + rr] = va.y;
                    As[(cc + 2) * GS + rr] = va.z; As[(cc + 3) * GS + rr] = va.w;
                    float4 vb = *(const float4*)&mct_x[(bj + rr) * DIM + k0 + cc];
                    Bs[(cc + 0) * GS + rr] = vb.x; Bs[(cc + 1) * GS + rr] = vb.y;
                    Bs[(cc + 2) * GS + rr] = vb.z; Bs[(cc + 3) * GS + rr] = vb.w;
                }
                __syncthreads();
#pragma unroll
                for (int k = 0; k < 32; k++) {
                    float4 av = *(const float4*)&As[k * GS + ty * 4];
                    float4 bv = *(const float4*)&Bs[k * GS + tx * 4];
                    acc[0][0] = fmaf(av.x, bv.x, acc[0][0]); acc[0][1] = fmaf(av.x, bv.y, acc[0][1]);
                    acc[0][2] = fmaf(av.x, bv.z, acc[0][2]); acc[0][3] = fmaf(av.x, bv.w, acc[0][3]);
                    acc[1][0] = fmaf(av.y, bv.x, acc[1][0]); acc[1][1] = fmaf(av.y, bv.y, acc[1][1]);
                    acc[1][2] = fmaf(av.y, bv.z, acc[1][2]); acc[1][3] = fmaf(av.y, bv.w, acc[1][3]);
                    acc[2][0] = fmaf(av.z, bv.x, acc[2][0]); acc[2][1] = fmaf(av.z, bv.y, acc[2][1]);
                    acc[2][2] = fmaf(av.z, bv.z, acc[2][2]); acc[2][3] = fmaf(av.z, bv.w, acc[2][3]);
                    acc[3][0] = fmaf(av.w, bv.x, acc[3][0]); acc[3][1] = fmaf(av.w, bv.y, acc[3][1]);
                    acc[3][2] = fmaf(av.w, bv.z, acc[3][2]); acc[3][3] = fmaf(av.w, bv.w, acc[3][3]);
                }
            }

            float xinv_c[4], fmag_c[4];
#pragma unroll
            for (int j = 0; j < 4; j++) {
                int col = bj + tx * 4 + j;
                xinv_c[j] = mct_xinv[col];
                fmag_c[j] = mct_fmag[col];
            }
#pragma unroll
            for (int i = 0; i < 4; i++) {
                int row = bi + ty * 4 + i;
                float av[4];
                float rs = 0.f;
#pragma unroll
                for (int j = 0; j < 4; j++) {
                    int col = bj + tx * 4 + j;
                    float s = acc[i][j] * xinv_c[j];
                    float dm = s - 1.f;
                    float a = (row == col) ? 0.f : __expf(CEXP * fmag_c[j] * dm * dm);
                    av[j] = a;
                    rs += a;
                }
                *(float4*)&mct_A[(size_t)row * NN + bj + tx * 4] = make_float4(av[0], av[1], av[2], av[3]);
#pragma unroll
                for (int o = 8; o; o >>= 1) rs += __shfl_xor_sync(0xffffffffu, rs, o);
                if ((lane & 15) == 0) atomicAdd(&mct_rowsum[row], rs);
            }
        }
    }

    grid_barrier(base + 2, bid, tid, true);

    // ================= phase 3: Neumann iteration (1 row/warp) + finalize =================
    {
        int r = 1 + bid * 8 + warp;           // 1..1024
        bool ok = (r <= NM);
        int rsafe = ok ? r : NM;
        const float4* Ar = (const float4*)(mct_A + (size_t)rsafe * NN);
        const float4* Arow0 = (const float4*)mct_A;

        float rs0inv = C0F / fmaxf(mct_rowsum[0], 1e-10f);
        float c0 = rs0inv * mct_A[rsafe];     // C0F * p0[r]
        float il = LAMBF / fmaxf(mct_rowsum[rsafe], 1e-10f);

        for (int it = 0; it < K_ITERS; it++) {
            float* xout = (it & 1) ? mct_v0 : mct_v1;

            float4 xv[8];
            if (it == 0) {
                // x0[j] = rs0inv * A[0][j]
#pragma unroll
                for (int k = 0; k < 8; k++) {
                    float4 a = __ldg(&Arow0[k * 32 + lane]);
                    xv[k] = make_float4(a.x * rs0inv, a.y * rs0inv, a.z * rs0inv, a.w * rs0inv);
                }
            } else {
                const float* xin = (it & 1) ? mct_v1 : mct_v0;
#pragma unroll
                for (int k = 0; k < 8; k++) xv[k] = ldv_f4(xin + (k * 32 + lane) * 4);
            }

            float da = 0.f, db = 0.f;
#pragma unroll
            for (int k = 0; k < 8; k += 2) {
                float4 m = Ar[k * 32 + lane];
                float4 n = Ar[(k + 1) * 32 + lane];
                da = fmaf(m.x, xv[k].x, da); da = fmaf(m.y, xv[k].y, da);
                da = fmaf(m.z, xv[k].z, da); da = fmaf(m.w, xv[k].w, da);
                db = fmaf(n.x, xv[k+1].x, db); db = fmaf(n.y, xv[k+1].y, db);
                db = fmaf(n.z, xv[k+1].z, db); db = fmaf(n.w, xv[k+1].w, db);
            }
            float d = da + db;
#pragma unroll
            for (int o = 16; o; o >>= 1) d += __shfl_xor_sync(0xffffffffu, d, o);
            if (lane == 0 && ok) xout[r] = fmaf(il, d, c0);

            grid_barrier(base + 3 + it, bid, tid, it < K_ITERS - 1);
        }
    }

    if (bid != 0) return;

    // ---- finalize (block 0): mean-center, clip, *100, softmax ----
    float4 vv = ldv_f4(mct_v0 + tid * 4);   // final iterate (K even); idx 0 pad = 0
    float vals[4] = {vv.x, vv.y, vv.z, vv.w};

    float s = vals[0] + vals[1] + vals[2] + vals[3];
#pragma unroll
    for (int o = 16; o; o >>= 1) s += __shfl_xor_sync(0xffffffffu, s, o);
    if (lane == 0) red[warp] = s;
    __syncthreads();
    if (warp == 0) {
        float x = (lane < 8) ? red[lane] : 0.f;
#pragma unroll
        for (int o = 4; o; o >>= 1) x += __shfl_xor_sync(0xffffffffu, x, o);
        if (lane == 0) red[0] = x;
    }
    __syncthreads();
    float mean = red[0] / (float)NM;
    __syncthreads();

    float z[4];
#pragma unroll
    for (int q = 0; q < 4; q++) {
        int idx = tid * 4 + q;
        z[q] = (idx >= 1) ? fmaxf(vals[q] - mean, 0.f) * 100.f : 0.f;
    }

    float m = fmaxf(fmaxf(z[0], z[1]), fmaxf(z[2], z[3]));
#pragma unroll
    for (int o = 16; o; o >>= 1) m = fmaxf(m, __shfl_xor_sync(0xffffffffu, m, o));
    if (lane == 0) red[warp] = m;
    __syncthreads();
    if (warp == 0) {
        float x = (lane < 8) ? red[lane] : 0.f;
#pragma unroll
        for (int o = 4; o; o >>= 1) x = fmaxf(x, __shfl_xor_sync(0xffffffffu, x, o));
        if (lane == 0) red[0] = x;
    }
    __syncthreads();
    float mx = red[0];
    __syncthreads();

    float e[4];
    float se = 0.f;
#pragma unroll
    for (int q = 0; q < 4; q++) {
        int idx = tid * 4 + q;
        e[q] = (idx >= 1) ? expf(z[q] - mx) : 0.f;
        se += e[q];
    }
#pragma unroll
    for (int o = 16; o; o >>= 1) se += __shfl_xor_sync(0xffffffffu, se, o);
    if (lane == 0) red[warp] = se;
    __syncthreads();
    if (warp == 0) {
        float x = (lane < 8) ? red[lane] : 0.f;
#pragma unroll
        for (int o = 4; o; o >>= 1) x += __shfl_xor_sync(0xffffffffu, x, o);
        if (lane == 0) red[0] = x;
    }
    __syncthreads();
    float inv = 1.f / red[0];

#pragma unroll
    for (int q = 0; q < 4; q++) {
        int idx = tid * 4 + q;
        if (idx >= 1) out[idx - 1] = e[q] * inv;
    }
}

// ---------------- launch ----------------
extern "C" void kernel_launch(void* const* d_in, const int* in_sizes, int n_in,
                              void* d_out, int out_size)
{
    const float* f  = (const float*)d_in[0];
    const float* w1 = (const float*)d_in[1]; const float* b1 = (const float*)d_in[2];
    const float* w2 = (const float*)d_in[3]; const float* b2 = (const float*)d_in[4];
    const float* w3 = (const float*)d_in[5]; const float* b3 = (const float*)d_in[6];
    const float* w4 = (const float*)d_in[7]; const float* b4 = (const float*)d_in[8];
    float* out = (float*)d_out;

    const int smem = (DIM * WS + 2 * MR * DIM) * (int)sizeof(float);   // 75776 B (covers gemm's 2*32*68)
    cudaFuncSetAttribute(fused_kernel, cudaFuncAttributeMaxDynamicSharedMemorySize, smem);

    fused_kernel<<<NBLK, THR, smem>>>(out, f, w1, b1, w2, b2, w3, b3, w4, b4);
}